// round 13
// baseline (speedup 1.0000x reference)
#include <cuda_runtime.h>
#include <stdint.h>
#include <math.h>

#define BB   128
#define TT   1024
#define DD   128
#define HH   256
#define G4H  1024

// Scan: 8 batch-groups x 8 N-slice CTAs = 64 CTAs, 512 threads each
#define NBG  8
#define NNC  8
#define BSUB 16          // batch rows per group
#define HC   32          // h columns per CTA (256/8)
#define NR   128         // gate cols per CTA (4*HC), j-major: p = j_local*4 + gate
#define STH  512
#define KS   264         // smem row stride (words); mod 32 == 8 (conflict-free)
#define NGEMM 4096

__device__ float    g_XGa[(size_t)BB * TT * G4H];
__device__ float    g_XGb[(size_t)BB * TT * G4H];
__device__ float    g_Y0[(size_t)BB * TT * HH];
__device__ float    g_Y1[(size_t)BB * TT * HH];
__device__ float    g_h[2][BB * HH];
__device__ unsigned g_flags[NBG][NNC * 8];      // 8 groups x 8 CTAs (32B-spaced)

__global__ void reset_kernel() {
    if (threadIdx.x < NBG * NNC * 8)
        reinterpret_cast<unsigned*>(g_flags)[threadIdx.x] = 0u;
}

__device__ __forceinline__ float to_tf32(float x) {
    float r;
    asm("cvt.rna.tf32.f32 %0, %1;" : "=f"(r) : "f"(x));
    return r;
}
__device__ __forceinline__ float sigf(float x) { return 1.f / (1.f + __expf(-x)); }
__device__ __forceinline__ float tanh_fast(float x) { return 2.f / (1.f + __expf(-2.f * x)) - 1.f; }

__device__ __forceinline__ void mma_tf32(float& c0, float& c1, float& c2, float& c3,
                                         uint32_t a0, uint32_t a1, uint32_t a2, uint32_t a3,
                                         uint32_t b0, uint32_t b1) {
    asm volatile(
        "mma.sync.aligned.m16n8k8.row.col.f32.tf32.tf32.f32 "
        "{%0,%1,%2,%3}, {%4,%5,%6,%7}, {%8,%9}, {%0,%1,%2,%3};\n"
        : "+f"(c0), "+f"(c1), "+f"(c2), "+f"(c3)
        : "r"(a0), "r"(a1), "r"(a2), "r"(a3), "r"(b0), "r"(b1));
}

__device__ __forceinline__ void st_release(unsigned* p, unsigned v) {
    asm volatile("st.release.gpu.global.u32 [%0], %1;" :: "l"(p), "r"(v) : "memory");
}
__device__ __forceinline__ unsigned ld_acquire(unsigned* p) {
    unsigned v;
    asm volatile("ld.acquire.gpu.global.u32 %0, [%1];" : "=r"(v) : "l"(p) : "memory");
    return v;
}
__device__ __forceinline__ void cp_async16(uint32_t smem_addr, const void* gptr) {
    asm volatile("cp.async.cg.shared.global [%0], [%1], 16;" :: "r"(smem_addr), "l"(gptr));
}
__device__ __forceinline__ void cp_commit() { asm volatile("cp.async.commit_group;" ::: "memory"); }
template <int N>
__device__ __forceinline__ void cp_wait() { asm volatile("cp.async.wait_group %0;" :: "n"(N) : "memory"); }

__device__ __forceinline__ int kslot(int k) {
    return (k & ~7) + (((k & 3) << 1) | ((k >> 2) & 1));
}

// ============================================================================
// GEMM core (512 threads): 128m x 256n CTA tile over K, cp.async dbl-buffered.
// 16 warps = 2m x 8n, warp m64 x n32. Out in permuted j-major gate columns.
// ============================================================================
template <int K>
__device__ __forceinline__ void gemm_tile(
    float* smbase, const float* __restrict__ In, float* __restrict__ Out,
    const float* __restrict__ Wih,
    const float* __restrict__ bih, const float* __restrict__ bhh,
    int m0, int n0, int tid)
{
    constexpr int KC  = 64;
    constexpr int KSg = 72;
    constexpr int NC  = K / KC;
    float* As   = smbase;                     // [2][128][72]
    float* Bs   = As + 2 * 128 * KSg;         // [2][256][72]
    float* bias = Bs + 2 * 256 * KSg;         // [256]

    if (tid < 256) {
        int P  = n0 + tid;
        int bx = (P & 3) * HH + (P >> 2);
        bias[tid] = bih[bx] + bhh[bx];
    }

    const uint32_t sA = (uint32_t)__cvta_generic_to_shared(As);
    const uint32_t sB = (uint32_t)__cvta_generic_to_shared(Bs);

    auto stage = [&](int c) {
        int buf = c & 1;
        uint32_t dA = sA + (uint32_t)(buf * 128 * KSg) * 4;
        uint32_t dB = sB + (uint32_t)(buf * 256 * KSg) * 4;
        for (int idx = tid; idx < 128 * (KC / 4); idx += STH) {
            int r = idx >> 4, k4 = idx & 15;
            cp_async16(dA + (uint32_t)(r * KSg + k4 * 4) * 4,
                       In + (size_t)(m0 + r) * K + c * KC + k4 * 4);
        }
        for (int idx = tid; idx < 256 * (KC / 4); idx += STH) {
            int n = idx >> 4, k4 = idx & 15;
            int P  = n0 + n;
            int rw = (P & 3) * HH + (P >> 2);
            cp_async16(dB + (uint32_t)(n * KSg + k4 * 4) * 4,
                       Wih + (size_t)rw * K + c * KC + k4 * 4);
        }
        cp_commit();
    };

    const int lane = tid & 31, wid = tid >> 5;
    const int wm = wid >> 3, wn = wid & 7;     // 2(m) x 8(n)
    const int grp = lane >> 2, tg = lane & 3;

    float acc[4][4][4];
#pragma unroll
    for (int mi = 0; mi < 4; ++mi)
#pragma unroll
        for (int ni = 0; ni < 4; ++ni)
#pragma unroll
            for (int q = 0; q < 4; ++q) acc[mi][ni][q] = 0.f;

    stage(0);

    for (int c = 0; c < NC; ++c) {
        if (c + 1 < NC) { stage(c + 1); cp_wait<1>(); }
        else           { cp_wait<0>(); }
        __syncthreads();

        const int buf = c & 1;
        const uint32_t* Ap = reinterpret_cast<const uint32_t*>(
            &As[buf * 128 * KSg + (wm * 64 + grp) * KSg + tg]);
        const uint32_t* Bp = reinterpret_cast<const uint32_t*>(
            &Bs[buf * 256 * KSg + (wn * 32 + grp) * KSg + tg]);

#pragma unroll
        for (int kt = 0; kt < KC / 8; ++kt) {
            uint32_t a[4][4];
#pragma unroll
            for (int mi = 0; mi < 4; ++mi) {
                const uint32_t* p = Ap + mi * 16 * KSg + kt * 8;
                a[mi][0] = p[0]; a[mi][1] = p[8 * KSg];
                a[mi][2] = p[4]; a[mi][3] = p[8 * KSg + 4];
            }
#pragma unroll
            for (int ni = 0; ni < 4; ++ni) {
                const uint32_t* q = Bp + ni * 8 * KSg + kt * 8;
                uint32_t b0 = q[0], b1 = q[4];
#pragma unroll
                for (int mi = 0; mi < 4; ++mi)
                    mma_tf32(acc[mi][ni][0], acc[mi][ni][1], acc[mi][ni][2], acc[mi][ni][3],
                             a[mi][0], a[mi][1], a[mi][2], a[mi][3], b0, b1);
            }
        }
        __syncthreads();
    }

#pragma unroll
    for (int mi = 0; mi < 4; ++mi)
#pragma unroll
        for (int ni = 0; ni < 4; ++ni) {
            int rl = wm * 64 + mi * 16 + grp;
            int cl = wn * 32 + ni * 8 + 2 * tg;
            float b0 = bias[cl], b1 = bias[cl + 1];
            size_t o = (size_t)(m0 + rl) * G4H + (n0 + cl);
            *reinterpret_cast<float2*>(&Out[o]) =
                make_float2(acc[mi][ni][0] + b0, acc[mi][ni][1] + b1);
            *reinterpret_cast<float2*>(&Out[o + (size_t)8 * G4H]) =
                make_float2(acc[mi][ni][2] + b0, acc[mi][ni][3] + b1);
        }
}

// Standalone xg GEMM for layer 0 (K = DD, reads x, writes g_XGa)
__global__ void __launch_bounds__(STH, 1)
xg0_kernel(const float* __restrict__ x, const float* __restrict__ Wih,
           const float* __restrict__ bih, const float* __restrict__ bhh)
{
    extern __shared__ float sm[];
    gemm_tile<DD>(sm, x, g_XGa, Wih, bih, bhh,
                  blockIdx.y * 128, blockIdx.x * 256, threadIdx.x);
}

// ============================================================================
// Mega kernel: blockIdx < 64 -> LSTM scan (layer l). blockIdx >= 64 -> gated
// xg GEMM for layer l+1. Flags are MONOTONIC across layers (base = l*TT).
// ============================================================================
__global__ void __launch_bounds__(STH, 1)
mega_kernel(int ysel, unsigned base,
            const float* __restrict__ Whh,
            const float* __restrict__ WihN,
            const float* __restrict__ bihN, const float* __restrict__ bhhN)
{
    extern __shared__ float sm[];
    float* Ydst = (ysel == 0) ? g_Y0 : g_Y1;
    const float* xgscan = (ysel == 0) ? g_XGa : g_XGb;
    float*       xgnext = (ysel == 0) ? g_XGb : g_XGa;
    const int tid = threadIdx.x;

    if (blockIdx.x >= NBG * NNC) {
        // ================= gated xg GEMM for layer l+1 =================
        const int g   = blockIdx.x - NBG * NNC;
        const int tc  = g >> 9;           // time chunk 0..7 (earliest first)
        const int rem = g & 511;
        const int b   = rem >> 2;         // batch row 0..127
        const int nb  = rem & 3;          // n-block 0..3
        const int m0  = b * TT + tc * 128;
        const int n0  = nb * 256;

        if (tid < 32) {
            const unsigned need = base + (unsigned)((tc + 1) * 128);
            const int bgg = b >> 4;
            bool done;
            do {
                unsigned v = 0xffffffffu;
                if (tid < NNC) v = ld_acquire(&g_flags[bgg][tid * 8]);
                done = __all_sync(0xffffffffu, v >= need);
                if (!done) __nanosleep(256);
            } while (!done);
        }
        __syncthreads();

        gemm_tile<HH>(sm, Ydst, xgnext, WihN, bihN, bhhN, m0, n0, tid);
        return;
    }

    // ======================= LSTM scan (layer l) =======================
    float* Wsm = sm;              // [NR][KS]   tf32 weight slab (~135 KB)
    float* Usm = Wsm + NR * KS;   // [BSUB][KS] h_{t-1} (tf32, pair-interleaved)
    float* Hs  = Usm + BSUB * KS; // [BSUB*HC]  tf32-interleaved h bounce

    const int cta = blockIdx.x;
    const int bg  = cta / NNC;
    const int nc  = cta % NNC;
    const int rb0 = bg * BSUB;
    unsigned* myflag = &g_flags[bg][nc * 8];

    // ---- Weight slab (j-major permuted rows, pair-interleaved k), tf32
    for (int idx = tid; idx < NR * HH; idx += STH) {
        int rl = idx >> 8, k = idx & 255;
        int rw = (rl & 3) * HH + (nc * HC + (rl >> 2));
        Wsm[rl * KS + kslot(k)] = to_tf32(Whh[(size_t)rw * HH + k]);
    }
    for (int idx = tid * 4; idx < BSUB * KS; idx += STH * 4)
        *reinterpret_cast<float4*>(&Usm[idx]) = make_float4(0.f, 0.f, 0.f, 0.f);
    __syncthreads();

    const int lane = tid & 31, wid = tid >> 5;     // wid = n8-tile index (0..15)
    const int grp = lane >> 2, tg = lane & 3;

    const uint32_t* Ua0 = reinterpret_cast<const uint32_t*>(&Usm[grp * KS + 2 * tg]);
    const uint32_t* Ua1 = Ua0 + 8 * KS;
    const uint32_t* Wb  = reinterpret_cast<const uint32_t*>(&Wsm[(wid * 8 + grp) * KS + 2 * tg]);

    // ---- Hoist W fragments into registers (32 k-blocks x uint2)
    uint2 wreg[32];
#pragma unroll
    for (int ib = 0; ib < 32; ++ib)
        wreg[ib] = *reinterpret_cast<const uint2*>(Wb + ib * 8);

    const int bA   = rb0 + grp;                    // batch row of accum rows c0,c1
    const int colP = nc * NR + wid * 8 + 2 * tg;   // permuted gate column of c0
    const float* xgA = xgscan + (size_t)bA * TT * G4H + colP;
    const float* xgB = xgA + (size_t)8 * TT * G4H; // batch row bA+8 (c2,c3)

    const bool odd  = (tg & 1);
    const int bl    = grp + (odd ? 8 : 0);         // local batch row this lane owns
    const int jl    = 2 * wid + (tg >> 1);         // local h-col this lane owns (0..31)
    const int jslot = (jl & ~7) + (((jl & 3) << 1) | ((jl >> 2) & 1));

    // coalesced-store mapping: thread i -> (b = i>>5, col-slot = i&31)
    const int sb = tid >> 5, sj = tid & 31;
    float* hout0 = &g_h[0][(rb0 + sb) * HH + nc * HC + sj];
    float* hout1 = &g_h[1][(rb0 + sb) * HH + nc * HC + sj];
    // scattered Y store by owner (published before release for the gemm gate)
    float* yown  = &Ydst[(size_t)(rb0 + bl) * TT * HH + nc * HC + jl];

    // staging mapping: thread -> row (tid>>5), 8 cols starting at (tid&31)*8
    const int strow = tid >> 5;
    const int stk0  = (tid & 31) * 8;

    float c_state = 0.f;

    float2 x01 = *reinterpret_cast<const float2*>(xgA);
    float2 x23 = *reinterpret_cast<const float2*>(xgB);

    for (int t = 0; t < TT; ++t) {
        // ---- Stage h_{t-1} -> Usm : verbatim float4 copy (tf32+interleaved)
        if (t > 0) {
            const float* hrow = g_h[t & 1] + (size_t)(rb0 + strow) * HH + stk0;
            float* urow = &Usm[strow * KS + stk0];
            float4 v0 = __ldcg(reinterpret_cast<const float4*>(hrow));
            float4 v1 = __ldcg(reinterpret_cast<const float4*>(hrow + 4));
            *reinterpret_cast<float4*>(urow)     = v0;
            *reinterpret_cast<float4*>(urow + 4) = v1;
        }
        __syncthreads();

        // ---- Whh * h_{t-1}: m16 x n8, K=256 as 4 independent chains, W in regs
        float a0c[4], a1c[4], a2c[4], a3c[4];
        a0c[0] = x01.x; a1c[0] = x01.y; a2c[0] = x23.x; a3c[0] = x23.y;
#pragma unroll
        for (int c = 1; c < 4; ++c) { a0c[c] = 0.f; a1c[c] = 0.f; a2c[c] = 0.f; a3c[c] = 0.f; }

#pragma unroll
        for (int kk = 0; kk < 8; ++kk) {
#pragma unroll
            for (int c = 0; c < 4; ++c) {
                int ib = c * 8 + kk;
                uint2 u0 = *reinterpret_cast<const uint2*>(Ua0 + ib * 8);
                uint2 u1 = *reinterpret_cast<const uint2*>(Ua1 + ib * 8);
                mma_tf32(a0c[c], a1c[c], a2c[c], a3c[c],
                         u0.x, u1.x, u0.y, u1.y, wreg[ib].x, wreg[ib].y);
            }
        }
        float c0 = (a0c[0] + a0c[1]) + (a0c[2] + a0c[3]);
        float c1 = (a1c[0] + a1c[1]) + (a1c[2] + a1c[3]);
        float c2 = (a2c[0] + a2c[1]) + (a2c[2] + a2c[3]);
        float c3 = (a3c[0] + a3c[1]) + (a3c[2] + a3c[3]);

        // ---- Gate exchange within lane pair (tg, tg^1)
        float s0 = odd ? c0 : c2;
        float s1 = odd ? c1 : c3;
        float r0 = __shfl_xor_sync(0xffffffffu, s0, 1);
        float r1 = __shfl_xor_sync(0xffffffffu, s1, 1);
        float iv = odd ? r0 : c0;
        float fv = odd ? r1 : c1;
        float gv = odd ? c2 : r0;
        float ov = odd ? c3 : r1;

        float is = sigf(iv);
        float fs = sigf(fv);
        float gt = tanh_fast(gv);
        float os = sigf(ov);
        c_state = fs * c_state + is * gt;
        float hn = os * tanh_fast(c_state);

        Hs[bl * HC + jslot] = to_tf32(hn);
        __syncthreads();

        // ---- Coalesced h store (128B row segments) + Y publish
        float hv = Hs[sb * HC + sj];
        if (t & 1) hout0[0] = hv; else hout1[0] = hv;
        yown[(size_t)t * HH] = hn;
        __syncthreads();

        if (tid == 0) st_release(myflag, base + (unsigned)(t + 1));

        // ---- xg prefetch overlaps the barrier wait
        if (t + 1 < TT) {
            xgA += G4H; xgB += G4H;
            x01 = *reinterpret_cast<const float2*>(xgA);
            x23 = *reinterpret_cast<const float2*>(xgB);
        }

        // ---- Poll all 8 group flags (warp 0)
        if (wid == 0) {
            const unsigned tgt = base + (unsigned)(t + 1);
            bool done;
            do {
                unsigned v = 0xffffffffu;
                if (lane < NNC) v = ld_acquire(&g_flags[bg][lane * 8]);
                done = __all_sync(0xffffffffu, v >= tgt);
            } while (!done);
        }
        __syncthreads();
    }
}

// Final FC: out[b*T + t] = dot(Y0[b,t,:], fc_W) + fc_b. One warp per row.
__global__ void __launch_bounds__(256)
fc_kernel(const float* __restrict__ w, const float* __restrict__ bptr,
          float* __restrict__ out)
{
    int row  = blockIdx.x * 8 + (threadIdx.x >> 5);
    int lane = threadIdx.x & 31;
    const float* yr = g_Y0 + (size_t)row * HH;
    float4 a0 = *reinterpret_cast<const float4*>(yr + lane * 4);
    float4 a1 = *reinterpret_cast<const float4*>(yr + 128 + lane * 4);
    float4 w0 = *reinterpret_cast<const float4*>(w + lane * 4);
    float4 w1 = *reinterpret_cast<const float4*>(w + 128 + lane * 4);
    float s = a0.x * w0.x + a0.y * w0.y + a0.z * w0.z + a0.w * w0.w
            + a1.x * w1.x + a1.y * w1.y + a1.z * w1.z + a1.w * w1.w;
#pragma unroll
    for (int off = 16; off > 0; off >>= 1)
        s += __shfl_xor_sync(0xffffffffu, s, off);
    if (lane == 0) out[row] = s + bptr[0];
}

extern "C" void kernel_launch(void* const* d_in, const int* in_sizes, int n_in,
                              void* d_out, int out_size)
{
    const float* x        = (const float*)d_in[0];
    const float* Wih0     = (const float*)d_in[1];
    const float* Whh0     = (const float*)d_in[2];
    const float* Wih_rest = (const float*)d_in[3];
    const float* Whh_rest = (const float*)d_in[4];
    const float* bih      = (const float*)d_in[5];
    const float* bhh      = (const float*)d_in[6];
    const float* fcW      = (const float*)d_in[7];
    const float* fcb      = (const float*)d_in[8];
    float* out = (float*)d_out;

    size_t gsmem = (size_t)(2 * 128 * 72 + 2 * 256 * 72 + 256) * sizeof(float); // ~217 KB

    cudaFuncSetAttribute(xg0_kernel,
                         cudaFuncAttributeMaxDynamicSharedMemorySize, (int)gsmem);
    cudaFuncSetAttribute(mega_kernel,
                         cudaFuncAttributeMaxDynamicSharedMemorySize, (int)gsmem);

    // One flag reset per launch (flags monotonic across layers)
    reset_kernel<<<1, NBG * NNC * 8>>>();

    // Layer 0 xg: x (K=128) -> g_XGa
    dim3 ggrid(G4H / 256, (BB * TT) / 128);   // 4 x 1024
    xg0_kernel<<<ggrid, STH, gsmem>>>(x, Wih0, bih, bhh);

    for (int l = 0; l < 5; ++l) {
        const float* Whh  = (l == 0) ? Whh0 : (Whh_rest + (size_t)(l - 1) * G4H * HH);
        const float* WihN = (l < 4) ? (Wih_rest + (size_t)l * G4H * HH) : Wih_rest;
        const float* biN  = bih + (size_t)((l < 4) ? (l + 1) : l) * G4H;
        const float* bhN  = bhh + (size_t)((l < 4) ? (l + 1) : l) * G4H;

        int nblocks = (l < 4) ? (NBG * NNC + NGEMM) : (NBG * NNC);
        mega_kernel<<<nblocks, STH, gsmem>>>(
            /*ysel=*/l & 1, /*base=*/(unsigned)(l * TT), Whh, WihN, biN, bhN);
    }

    // Layer 4 wrote Y0. FC head.
    fc_kernel<<<(BB * TT) / 8, 256>>>(fcW, fcb, out);
}

// round 14
// speedup vs baseline: 1.1477x; 1.1477x over previous
#include <cuda_runtime.h>
#include <stdint.h>
#include <math.h>

#define BB   128
#define TT   1024
#define DD   128
#define HH   256
#define G4H  1024

// Scan: 8 batch-groups x 16 N-slice CTAs = 128 CTAs, 256 threads each (R12 shape)
#define NBG  8
#define NNC  16
#define BSUB 16
#define HC   16
#define NR   64
#define NTHREADS 256
#define KS   264
#define NGEMM 4096

__device__ float    g_XGa[(size_t)BB * TT * G4H];
__device__ float    g_XGb[(size_t)BB * TT * G4H];
__device__ float    g_Y0[(size_t)BB * TT * HH];
__device__ float    g_Y1[(size_t)BB * TT * HH];
__device__ float    g_h[2][BB * HH];
__device__ unsigned g_flags[NBG][NNC * 8];

__global__ void reset_kernel() {
    if (threadIdx.x < NBG * NNC * 8)
        reinterpret_cast<unsigned*>(g_flags)[threadIdx.x] = 0u;
}

__device__ __forceinline__ float to_tf32(float x) {
    float r;
    asm("cvt.rna.tf32.f32 %0, %1;" : "=f"(r) : "f"(x));
    return r;
}
__device__ __forceinline__ float sigf(float x) { return 1.f / (1.f + __expf(-x)); }
__device__ __forceinline__ float tanh_fast(float x) { return 2.f / (1.f + __expf(-2.f * x)) - 1.f; }

__device__ __forceinline__ void mma_tf32(float& c0, float& c1, float& c2, float& c3,
                                         uint32_t a0, uint32_t a1, uint32_t a2, uint32_t a3,
                                         uint32_t b0, uint32_t b1) {
    asm volatile(
        "mma.sync.aligned.m16n8k8.row.col.f32.tf32.tf32.f32 "
        "{%0,%1,%2,%3}, {%4,%5,%6,%7}, {%8,%9}, {%0,%1,%2,%3};\n"
        : "+f"(c0), "+f"(c1), "+f"(c2), "+f"(c3)
        : "r"(a0), "r"(a1), "r"(a2), "r"(a3), "r"(b0), "r"(b1));
}

__device__ __forceinline__ void st_release(unsigned* p, unsigned v) {
    asm volatile("st.release.gpu.global.u32 [%0], %1;" :: "l"(p), "r"(v) : "memory");
}
__device__ __forceinline__ unsigned ld_acquire(unsigned* p) {
    unsigned v;
    asm volatile("ld.acquire.gpu.global.u32 %0, [%1];" : "=r"(v) : "l"(p) : "memory");
    return v;
}
__device__ __forceinline__ void cp_async16(uint32_t smem_addr, const void* gptr) {
    asm volatile("cp.async.cg.shared.global [%0], [%1], 16;" :: "r"(smem_addr), "l"(gptr));
}
__device__ __forceinline__ void cp_commit() { asm volatile("cp.async.commit_group;" ::: "memory"); }
template <int N>
__device__ __forceinline__ void cp_wait() { asm volatile("cp.async.wait_group %0;" :: "n"(N) : "memory"); }

__device__ __forceinline__ int kslot(int k) {
    return (k & ~7) + (((k & 3) << 1) | ((k >> 2) & 1));
}

// ============================================================================
// GEMM core (256 threads, R12-proven): 128m x 256n over K, cp.async KC=64.
// ============================================================================
template <int K>
__device__ __forceinline__ void gemm_tile(
    float* smbase, const float* __restrict__ In, float* __restrict__ Out,
    const float* __restrict__ Wih,
    const float* __restrict__ bih, const float* __restrict__ bhh,
    int m0, int n0, int tid)
{
    constexpr int KC  = 64;
    constexpr int KSg = 72;
    constexpr int NC  = K / KC;
    float* As   = smbase;
    float* Bs   = As + 2 * 128 * KSg;
    float* bias = Bs + 2 * 256 * KSg;

    if (tid < 256) {
        int P  = n0 + tid;
        int bx = (P & 3) * HH + (P >> 2);
        bias[tid] = bih[bx] + bhh[bx];
    }

    const uint32_t sA = (uint32_t)__cvta_generic_to_shared(As);
    const uint32_t sB = (uint32_t)__cvta_generic_to_shared(Bs);

    auto stage = [&](int c) {
        int buf = c & 1;
        uint32_t dA = sA + (uint32_t)(buf * 128 * KSg) * 4;
        uint32_t dB = sB + (uint32_t)(buf * 256 * KSg) * 4;
        for (int idx = tid; idx < 128 * (KC / 4); idx += 256) {
            int r = idx >> 4, k4 = idx & 15;
            cp_async16(dA + (uint32_t)(r * KSg + k4 * 4) * 4,
                       In + (size_t)(m0 + r) * K + c * KC + k4 * 4);
        }
        for (int idx = tid; idx < 256 * (KC / 4); idx += 256) {
            int n = idx >> 4, k4 = idx & 15;
            int P  = n0 + n;
            int rw = (P & 3) * HH + (P >> 2);
            cp_async16(dB + (uint32_t)(n * KSg + k4 * 4) * 4,
                       Wih + (size_t)rw * K + c * KC + k4 * 4);
        }
        cp_commit();
    };

    const int lane = tid & 31, wid = tid >> 5;
    const int wm = wid >> 2, wn = wid & 3;
    const int grp = lane >> 2, tg = lane & 3;

    float acc[4][8][4];
#pragma unroll
    for (int mi = 0; mi < 4; ++mi)
#pragma unroll
        for (int ni = 0; ni < 8; ++ni)
#pragma unroll
            for (int q = 0; q < 4; ++q) acc[mi][ni][q] = 0.f;

    stage(0);

    for (int c = 0; c < NC; ++c) {
        if (c + 1 < NC) { stage(c + 1); cp_wait<1>(); }
        else           { cp_wait<0>(); }
        __syncthreads();

        const int buf = c & 1;
        const uint32_t* Ap = reinterpret_cast<const uint32_t*>(
            &As[buf * 128 * KSg + (wm * 64 + grp) * KSg + tg]);
        const uint32_t* Bp = reinterpret_cast<const uint32_t*>(
            &Bs[buf * 256 * KSg + (wn * 64 + grp) * KSg + tg]);

#pragma unroll
        for (int kt = 0; kt < KC / 8; ++kt) {
            uint32_t a[4][4];
#pragma unroll
            for (int mi = 0; mi < 4; ++mi) {
                const uint32_t* p = Ap + mi * 16 * KSg + kt * 8;
                a[mi][0] = p[0]; a[mi][1] = p[8 * KSg];
                a[mi][2] = p[4]; a[mi][3] = p[8 * KSg + 4];
            }
#pragma unroll
            for (int ni = 0; ni < 8; ++ni) {
                const uint32_t* q = Bp + ni * 8 * KSg + kt * 8;
                uint32_t b0 = q[0], b1 = q[4];
#pragma unroll
                for (int mi = 0; mi < 4; ++mi)
                    mma_tf32(acc[mi][ni][0], acc[mi][ni][1], acc[mi][ni][2], acc[mi][ni][3],
                             a[mi][0], a[mi][1], a[mi][2], a[mi][3], b0, b1);
            }
        }
        __syncthreads();
    }

#pragma unroll
    for (int mi = 0; mi < 4; ++mi)
#pragma unroll
        for (int ni = 0; ni < 8; ++ni) {
            int rl = wm * 64 + mi * 16 + grp;
            int cl = wn * 64 + ni * 8 + 2 * tg;
            float b0 = bias[cl], b1 = bias[cl + 1];
            size_t o = (size_t)(m0 + rl) * G4H + (n0 + cl);
            *reinterpret_cast<float2*>(&Out[o]) =
                make_float2(acc[mi][ni][0] + b0, acc[mi][ni][1] + b1);
            *reinterpret_cast<float2*>(&Out[o + (size_t)8 * G4H]) =
                make_float2(acc[mi][ni][2] + b0, acc[mi][ni][3] + b1);
        }
}

// Standalone xg GEMM for layer 0 (K = DD, reads x, writes g_XGa)
__global__ void __launch_bounds__(256, 1)
xg0_kernel(const float* __restrict__ x, const float* __restrict__ Wih,
           const float* __restrict__ bih, const float* __restrict__ bhh)
{
    extern __shared__ float sm[];
    gemm_tile<DD>(sm, x, g_XGa, Wih, bih, bhh,
                  blockIdx.y * 128, blockIdx.x * 256, threadIdx.x);
}

// ============================================================================
// Mega kernel: blockIdx < 128 -> LSTM scan (layer l). blockIdx >= 128 ->
// gated xg GEMM for layer l+1. Flags MONOTONIC across layers (base = l*TT).
// Scan uses FRONT-of-step per-warp poll+stage (overlap fetch with stragglers).
// ============================================================================
__global__ void __launch_bounds__(NTHREADS, 1)
mega_kernel(int ysel, unsigned base,
            const float* __restrict__ Whh,
            const float* __restrict__ WihN,
            const float* __restrict__ bihN, const float* __restrict__ bhhN)
{
    extern __shared__ float sm[];
    float* Ydst = (ysel == 0) ? g_Y0 : g_Y1;
    const float* xgscan = (ysel == 0) ? g_XGa : g_XGb;
    float*       xgnext = (ysel == 0) ? g_XGb : g_XGa;
    const int tid = threadIdx.x;

    if (blockIdx.x >= 128) {
        // ================= gated xg GEMM for layer l+1 =================
        const int g   = blockIdx.x - 128;
        const int tc  = g >> 9;
        const int rem = g & 511;
        const int b   = rem >> 2;
        const int nb  = rem & 3;
        const int m0  = b * TT + tc * 128;
        const int n0  = nb * 256;

        if (tid < 32) {
            const unsigned need = base + (unsigned)((tc + 1) * 128);
            const int bgg = b >> 4;
            bool done;
            do {
                unsigned v = 0xffffffffu;
                if (tid < NNC) v = ld_acquire(&g_flags[bgg][tid * 8]);
                done = __all_sync(0xffffffffu, v >= need);
                if (!done) __nanosleep(256);
            } while (!done);
        }
        __syncthreads();

        gemm_tile<HH>(sm, Ydst, xgnext, WihN, bihN, bhhN, m0, n0, tid);
        return;
    }

    // ======================= LSTM scan (layer l) =======================
    float* Wsm = sm;              // [NR][KS]
    float* Usm = Wsm + NR * KS;   // [BSUB][KS]
    float* Hs  = Usm + BSUB * KS; // [BSUB*HC]

    const int cta = blockIdx.x;
    const int bg  = cta / NNC;
    const int nc  = cta % NNC;
    const int rb0 = bg * BSUB;
    unsigned* myflag = &g_flags[bg][nc * 8];

    for (int idx = tid; idx < NR * HH; idx += NTHREADS) {
        int rl = idx >> 8, k = idx & 255;
        int rw = (rl & 3) * HH + (nc * HC + (rl >> 2));
        Wsm[rl * KS + kslot(k)] = to_tf32(Whh[(size_t)rw * HH + k]);
    }
    for (int idx = tid * 4; idx < BSUB * KS; idx += NTHREADS * 4)
        *reinterpret_cast<float4*>(&Usm[idx]) = make_float4(0.f, 0.f, 0.f, 0.f);
    __syncthreads();

    const int lane = tid & 31, wid = tid >> 5;
    const int grp = lane >> 2, tg = lane & 3;

    const uint32_t* Ua0 = reinterpret_cast<const uint32_t*>(&Usm[grp * KS + 2 * tg]);
    const uint32_t* Ua1 = Ua0 + 8 * KS;
    const uint32_t* Wb  = reinterpret_cast<const uint32_t*>(&Wsm[(wid * 8 + grp) * KS + 2 * tg]);

    uint2 wreg[32];
#pragma unroll
    for (int ib = 0; ib < 32; ++ib)
        wreg[ib] = *reinterpret_cast<const uint2*>(Wb + ib * 8);

    const int bA   = rb0 + grp;
    const int colP = nc * NR + wid * 8 + 2 * tg;
    const float* xgA = xgscan + (size_t)bA * TT * G4H + colP;
    const float* xgB = xgA + (size_t)8 * TT * G4H;

    const bool odd  = (tg & 1);
    const int bl    = grp + (odd ? 8 : 0);
    const int jl    = 2 * wid + (tg >> 1);
    const int jslot = (jl & ~7) + (((jl & 3) << 1) | ((jl >> 2) & 1));

    const int sb = tid >> 4, sj = tid & 15;
    float* hout0 = &g_h[0][(rb0 + sb) * HH + nc * HC + sj];
    float* hout1 = &g_h[1][(rb0 + sb) * HH + nc * HC + sj];
    float* yown  = &Ydst[(size_t)(rb0 + bl) * TT * HH + nc * HC + jl];

    // front-of-step staging mapping: warp wid handles producer slices 2*wid
    // and 2*wid + 1; lane -> (slice = 2*wid + (lane>>4), row = lane & 15)
    const int psl  = 2 * wid + (lane >> 4);       // producer slice this lane stages
    const int prow = lane & 15;                   // batch row within group
    unsigned* pflag = &g_flags[bg][psl * 8];
    const float* hsrc0 = g_h[0] + (size_t)(rb0 + prow) * HH + psl * 16;
    const float* hsrc1 = g_h[1] + (size_t)(rb0 + prow) * HH + psl * 16;
    float* udst = &Usm[prow * KS + psl * 16];

    float c_state = 0.f;

    float2 x01 = *reinterpret_cast<const float2*>(xgA);
    float2 x23 = *reinterpret_cast<const float2*>(xgB);

    for (int t = 0; t < TT; ++t) {
        // ---- FRONT: per-warp poll of this warp's 2 producers, then stage.
        // Early slices are fetched while straggler CTAs finish step t-1.
        if (t > 0) {
            const unsigned tgt = base + (unsigned)t;
            if ((lane & 15) == 0) {
                while (ld_acquire(pflag) < tgt) { }
            }
            __syncwarp();
            const float* hrow = (t & 1) ? hsrc1 : hsrc0;   // g_h[t&1]
#pragma unroll
            for (int q = 0; q < 4; ++q) {
                float4 v = __ldcg(reinterpret_cast<const float4*>(hrow + q * 4));
                *reinterpret_cast<float4*>(udst + q * 4) = v;
            }
        }
        __syncthreads();   // Usm ready (covers zero-init at t=0)

        // ---- Whh * h_{t-1}: m16 x n8, K=256 as 4 independent chains, W in regs
        float a0c[4], a1c[4], a2c[4], a3c[4];
        a0c[0] = x01.x; a1c[0] = x01.y; a2c[0] = x23.x; a3c[0] = x23.y;
#pragma unroll
        for (int c = 1; c < 4; ++c) { a0c[c] = 0.f; a1c[c] = 0.f; a2c[c] = 0.f; a3c[c] = 0.f; }

#pragma unroll
        for (int kk = 0; kk < 8; ++kk) {
#pragma unroll
            for (int c = 0; c < 4; ++c) {
                int ib = c * 8 + kk;
                uint2 u0 = *reinterpret_cast<const uint2*>(Ua0 + ib * 8);
                uint2 u1 = *reinterpret_cast<const uint2*>(Ua1 + ib * 8);
                mma_tf32(a0c[c], a1c[c], a2c[c], a3c[c],
                         u0.x, u1.x, u0.y, u1.y, wreg[ib].x, wreg[ib].y);
            }
        }
        float c0 = (a0c[0] + a0c[1]) + (a0c[2] + a0c[3]);
        float c1 = (a1c[0] + a1c[1]) + (a1c[2] + a1c[3]);
        float c2 = (a2c[0] + a2c[1]) + (a2c[2] + a2c[3]);
        float c3 = (a3c[0] + a3c[1]) + (a3c[2] + a3c[3]);

        // ---- Gate exchange within lane pair (tg, tg^1)
        float s0 = odd ? c0 : c2;
        float s1 = odd ? c1 : c3;
        float r0 = __shfl_xor_sync(0xffffffffu, s0, 1);
        float r1 = __shfl_xor_sync(0xffffffffu, s1, 1);
        float iv = odd ? r0 : c0;
        float fv = odd ? r1 : c1;
        float gv = odd ? c2 : r0;
        float ov = odd ? c3 : r1;

        float is = sigf(iv);
        float fs = sigf(fv);
        float gt = tanh_fast(gv);
        float os = sigf(ov);
        c_state = fs * c_state + is * gt;
        float hn = os * tanh_fast(c_state);

        Hs[bl * HC + jslot] = to_tf32(hn);
        __syncthreads();   // bounce complete (also: all MMA reads of Usm done)

        // ---- Coalesced h store + Y publish
        float hv = Hs[sb * HC + sj];
        if (t & 1) hout0[0] = hv; else hout1[0] = hv;   // write g_h[(t+1)&1]
        yown[(size_t)t * HH] = hn;
        __syncthreads();   // stores happen-before release

        if (tid == 0) st_release(myflag, base + (unsigned)(t + 1));

        // ---- xg prefetch overlaps next step's poll
        if (t + 1 < TT) {
            xgA += G4H; xgB += G4H;
            x01 = *reinterpret_cast<const float2*>(xgA);
            x23 = *reinterpret_cast<const float2*>(xgB);
        }
    }
}

// Final FC: out[b*T + t] = dot(Y0[b,t,:], fc_W) + fc_b. One warp per row.
__global__ void __launch_bounds__(256)
fc_kernel(const float* __restrict__ w, const float* __restrict__ bptr,
          float* __restrict__ out)
{
    int row  = blockIdx.x * 8 + (threadIdx.x >> 5);
    int lane = threadIdx.x & 31;
    const float* yr = g_Y0 + (size_t)row * HH;
    float4 a0 = *reinterpret_cast<const float4*>(yr + lane * 4);
    float4 a1 = *reinterpret_cast<const float4*>(yr + 128 + lane * 4);
    float4 w0 = *reinterpret_cast<const float4*>(w + lane * 4);
    float4 w1 = *reinterpret_cast<const float4*>(w + 128 + lane * 4);
    float s = a0.x * w0.x + a0.y * w0.y + a0.z * w0.z + a0.w * w0.w
            + a1.x * w1.x + a1.y * w1.y + a1.z * w1.z + a1.w * w1.w;
#pragma unroll
    for (int off = 16; off > 0; off >>= 1)
        s += __shfl_xor_sync(0xffffffffu, s, off);
    if (lane == 0) out[row] = s + bptr[0];
}

extern "C" void kernel_launch(void* const* d_in, const int* in_sizes, int n_in,
                              void* d_out, int out_size)
{
    const float* x        = (const float*)d_in[0];
    const float* Wih0     = (const float*)d_in[1];
    const float* Whh0     = (const float*)d_in[2];
    const float* Wih_rest = (const float*)d_in[3];
    const float* Whh_rest = (const float*)d_in[4];
    const float* bih      = (const float*)d_in[5];
    const float* bhh      = (const float*)d_in[6];
    const float* fcW      = (const float*)d_in[7];
    const float* fcb      = (const float*)d_in[8];
    float* out = (float*)d_out;

    size_t gsmem = (size_t)(2 * 128 * 72 + 2 * 256 * 72 + 256) * sizeof(float); // ~217 KB

    cudaFuncSetAttribute(xg0_kernel,
                         cudaFuncAttributeMaxDynamicSharedMemorySize, (int)gsmem);
    cudaFuncSetAttribute(mega_kernel,
                         cudaFuncAttributeMaxDynamicSharedMemorySize, (int)gsmem);

    // Single flag reset (flags are monotonic across layers)
    reset_kernel<<<1, NBG * NNC * 8>>>();

    // Layer 0 xg: x (K=128) -> g_XGa
    dim3 ggrid(G4H / 256, (BB * TT) / 128);   // 4 x 1024
    xg0_kernel<<<ggrid, 256, gsmem>>>(x, Wih0, bih, bhh);

    for (int l = 0; l < 5; ++l) {
        const float* Whh  = (l == 0) ? Whh0 : (Whh_rest + (size_t)(l - 1) * G4H * HH);
        const float* WihN = (l < 4) ? (Wih_rest + (size_t)l * G4H * HH) : Wih_rest;
        const float* biN  = bih + (size_t)((l < 4) ? (l + 1) : l) * G4H;
        const float* bhN  = bhh + (size_t)((l < 4) ? (l + 1) : l) * G4H;

        int nblocks = (l < 4) ? (128 + NGEMM) : 128;
        mega_kernel<<<nblocks, NTHREADS, gsmem>>>(
            /*ysel=*/l & 1, /*base=*/(unsigned)(l * TT), Whh, WihN, biN, bhN);
    }

    // Layer 4 wrote Y0. FC head.
    fc_kernel<<<(BB * TT) / 8, 256>>>(fcW, fcb, out);
}

// round 15
// speedup vs baseline: 1.1796x; 1.0278x over previous
#include <cuda_runtime.h>
#include <stdint.h>
#include <math.h>

#define BB   128
#define TT   1024
#define DD   128
#define HH   256
#define G4H  1024

// Scan: 8 batch-groups x 16 N-slice CTAs = 128 CTAs, 256 threads each
#define NBG  8
#define NNC  16
#define BSUB 16
#define HC   16
#define NR   64
#define NTHREADS 256
#define KS   264
#define NGEMM 4096
#define LSTRIDE (TT + 16)   // per-layer flag base stride (room for the +1 release)

__device__ float    g_XGa[(size_t)BB * TT * G4H];
__device__ float    g_XGb[(size_t)BB * TT * G4H];
__device__ float    g_Y0[(size_t)BB * TT * HH];
__device__ float    g_Y1[(size_t)BB * TT * HH];
__device__ float    g_h[2][BB * HH];
__device__ unsigned g_flags[NBG][NNC * 8];

__global__ void reset_kernel() {
    if (threadIdx.x < NBG * NNC * 8)
        reinterpret_cast<unsigned*>(g_flags)[threadIdx.x] = 0u;
}

__device__ __forceinline__ float to_tf32(float x) {
    float r;
    asm("cvt.rna.tf32.f32 %0, %1;" : "=f"(r) : "f"(x));
    return r;
}
__device__ __forceinline__ float sigf(float x) { return 1.f / (1.f + __expf(-x)); }
__device__ __forceinline__ float tanh_fast(float x) { return 2.f / (1.f + __expf(-2.f * x)) - 1.f; }

__device__ __forceinline__ void mma_tf32(float& c0, float& c1, float& c2, float& c3,
                                         uint32_t a0, uint32_t a1, uint32_t a2, uint32_t a3,
                                         uint32_t b0, uint32_t b1) {
    asm volatile(
        "mma.sync.aligned.m16n8k8.row.col.f32.tf32.tf32.f32 "
        "{%0,%1,%2,%3}, {%4,%5,%6,%7}, {%8,%9}, {%0,%1,%2,%3};\n"
        : "+f"(c0), "+f"(c1), "+f"(c2), "+f"(c3)
        : "r"(a0), "r"(a1), "r"(a2), "r"(a3), "r"(b0), "r"(b1));
}

__device__ __forceinline__ void st_release(unsigned* p, unsigned v) {
    asm volatile("st.release.gpu.global.u32 [%0], %1;" :: "l"(p), "r"(v) : "memory");
}
__device__ __forceinline__ unsigned ld_acquire(unsigned* p) {
    unsigned v;
    asm volatile("ld.acquire.gpu.global.u32 %0, [%1];" : "=r"(v) : "l"(p) : "memory");
    return v;
}
__device__ __forceinline__ void cp_async16(uint32_t smem_addr, const void* gptr) {
    asm volatile("cp.async.cg.shared.global [%0], [%1], 16;" :: "r"(smem_addr), "l"(gptr));
}
__device__ __forceinline__ void cp_commit() { asm volatile("cp.async.commit_group;" ::: "memory"); }
template <int N>
__device__ __forceinline__ void cp_wait() { asm volatile("cp.async.wait_group %0;" :: "n"(N) : "memory"); }

__device__ __forceinline__ int kslot(int k) {
    return (k & ~7) + (((k & 3) << 1) | ((k >> 2) & 1));
}

// ============================================================================
// GEMM core (256 threads): 128m x 256n over K, cp.async dbl-buffered KC=64.
// ============================================================================
template <int K>
__device__ __forceinline__ void gemm_tile(
    float* smbase, const float* __restrict__ In, float* __restrict__ Out,
    const float* __restrict__ Wih,
    const float* __restrict__ bih, const float* __restrict__ bhh,
    int m0, int n0, int tid)
{
    constexpr int KC  = 64;
    constexpr int KSg = 72;
    constexpr int NC  = K / KC;
    float* As   = smbase;
    float* Bs   = As + 2 * 128 * KSg;
    float* bias = Bs + 2 * 256 * KSg;

    if (tid < 256) {
        int P  = n0 + tid;
        int bx = (P & 3) * HH + (P >> 2);
        bias[tid] = bih[bx] + bhh[bx];
    }

    const uint32_t sA = (uint32_t)__cvta_generic_to_shared(As);
    const uint32_t sB = (uint32_t)__cvta_generic_to_shared(Bs);

    auto stage = [&](int c) {
        int buf = c & 1;
        uint32_t dA = sA + (uint32_t)(buf * 128 * KSg) * 4;
        uint32_t dB = sB + (uint32_t)(buf * 256 * KSg) * 4;
        for (int idx = tid; idx < 128 * (KC / 4); idx += 256) {
            int r = idx >> 4, k4 = idx & 15;
            cp_async16(dA + (uint32_t)(r * KSg + k4 * 4) * 4,
                       In + (size_t)(m0 + r) * K + c * KC + k4 * 4);
        }
        for (int idx = tid; idx < 256 * (KC / 4); idx += 256) {
            int n = idx >> 4, k4 = idx & 15;
            int P  = n0 + n;
            int rw = (P & 3) * HH + (P >> 2);
            cp_async16(dB + (uint32_t)(n * KSg + k4 * 4) * 4,
                       Wih + (size_t)rw * K + c * KC + k4 * 4);
        }
        cp_commit();
    };

    const int lane = tid & 31, wid = tid >> 5;
    const int wm = wid >> 2, wn = wid & 3;
    const int grp = lane >> 2, tg = lane & 3;

    float acc[4][8][4];
#pragma unroll
    for (int mi = 0; mi < 4; ++mi)
#pragma unroll
        for (int ni = 0; ni < 8; ++ni)
#pragma unroll
            for (int q = 0; q < 4; ++q) acc[mi][ni][q] = 0.f;

    stage(0);

    for (int c = 0; c < NC; ++c) {
        if (c + 1 < NC) { stage(c + 1); cp_wait<1>(); }
        else           { cp_wait<0>(); }
        __syncthreads();

        const int buf = c & 1;
        const uint32_t* Ap = reinterpret_cast<const uint32_t*>(
            &As[buf * 128 * KSg + (wm * 64 + grp) * KSg + tg]);
        const uint32_t* Bp = reinterpret_cast<const uint32_t*>(
            &Bs[buf * 256 * KSg + (wn * 64 + grp) * KSg + tg]);

#pragma unroll
        for (int kt = 0; kt < KC / 8; ++kt) {
            uint32_t a[4][4];
#pragma unroll
            for (int mi = 0; mi < 4; ++mi) {
                const uint32_t* p = Ap + mi * 16 * KSg + kt * 8;
                a[mi][0] = p[0]; a[mi][1] = p[8 * KSg];
                a[mi][2] = p[4]; a[mi][3] = p[8 * KSg + 4];
            }
#pragma unroll
            for (int ni = 0; ni < 8; ++ni) {
                const uint32_t* q = Bp + ni * 8 * KSg + kt * 8;
                uint32_t b0 = q[0], b1 = q[4];
#pragma unroll
                for (int mi = 0; mi < 4; ++mi)
                    mma_tf32(acc[mi][ni][0], acc[mi][ni][1], acc[mi][ni][2], acc[mi][ni][3],
                             a[mi][0], a[mi][1], a[mi][2], a[mi][3], b0, b1);
            }
        }
        __syncthreads();
    }

#pragma unroll
    for (int mi = 0; mi < 4; ++mi)
#pragma unroll
        for (int ni = 0; ni < 8; ++ni) {
            int rl = wm * 64 + mi * 16 + grp;
            int cl = wn * 64 + ni * 8 + 2 * tg;
            float b0 = bias[cl], b1 = bias[cl + 1];
            size_t o = (size_t)(m0 + rl) * G4H + (n0 + cl);
            *reinterpret_cast<float2*>(&Out[o]) =
                make_float2(acc[mi][ni][0] + b0, acc[mi][ni][1] + b1);
            *reinterpret_cast<float2*>(&Out[o + (size_t)8 * G4H]) =
                make_float2(acc[mi][ni][2] + b0, acc[mi][ni][3] + b1);
        }
}

// Standalone xg GEMM for layer 0 (K = DD, reads x, writes g_XGa)
__global__ void __launch_bounds__(256, 1)
xg0_kernel(const float* __restrict__ x, const float* __restrict__ Wih,
           const float* __restrict__ bih, const float* __restrict__ bhh)
{
    extern __shared__ float sm[];
    gemm_tile<DD>(sm, x, g_XGa, Wih, bih, bhh,
                  blockIdx.y * 128, blockIdx.x * 256, threadIdx.x);
}

// ============================================================================
// Mega kernel: blockIdx < 128 -> LSTM scan (layer l). blockIdx >= 128 ->
// gated xg GEMM for layer l+1 (gate = +1 step: Y published lazily).
// Flags MONOTONIC across layers (base = l*LSTRIDE).
// ============================================================================
__global__ void __launch_bounds__(NTHREADS, 1)
mega_kernel(int ysel, unsigned base,
            const float* __restrict__ Whh,
            const float* __restrict__ WihN,
            const float* __restrict__ bihN, const float* __restrict__ bhhN)
{
    extern __shared__ float sm[];
    float* Ydst = (ysel == 0) ? g_Y0 : g_Y1;
    const float* xgscan = (ysel == 0) ? g_XGa : g_XGb;
    float*       xgnext = (ysel == 0) ? g_XGb : g_XGa;
    const int tid = threadIdx.x;

    if (blockIdx.x >= 128) {
        // ============ gated xg GEMM for layer l+1 (lazy-Y gate: +1) ============
        const int g   = blockIdx.x - 128;
        const int tc  = g >> 9;
        const int rem = g & 511;
        const int b   = rem >> 2;
        const int nb  = rem & 3;
        const int m0  = b * TT + tc * 128;
        const int n0  = nb * 256;

        if (tid < 32) {
            const unsigned need = base + (unsigned)((tc + 1) * 128 + 1);
            const int bgg = b >> 4;
            bool done;
            do {
                unsigned v = 0xffffffffu;
                if (tid < NNC) v = ld_acquire(&g_flags[bgg][tid * 8]);
                done = __all_sync(0xffffffffu, v >= need);
                if (!done) __nanosleep(256);
            } while (!done);
        }
        __syncthreads();

        gemm_tile<HH>(sm, Ydst, xgnext, WihN, bihN, bhhN, m0, n0, tid);
        return;
    }

    // ======================= LSTM scan (layer l) =======================
    float* Wsm = sm;              // [NR][KS]
    float* Usm = Wsm + NR * KS;   // [BSUB][KS]
    float* Hs  = Usm + BSUB * KS; // [BSUB*HC]

    const int cta = blockIdx.x;
    const int bg  = cta / NNC;
    const int nc  = cta % NNC;
    const int rb0 = bg * BSUB;
    unsigned* myflag = &g_flags[bg][nc * 8];

    for (int idx = tid; idx < NR * HH; idx += NTHREADS) {
        int rl = idx >> 8, k = idx & 255;
        int rw = (rl & 3) * HH + (nc * HC + (rl >> 2));
        Wsm[rl * KS + kslot(k)] = to_tf32(Whh[(size_t)rw * HH + k]);
    }
    for (int idx = tid * 4; idx < BSUB * KS; idx += NTHREADS * 4)
        *reinterpret_cast<float4*>(&Usm[idx]) = make_float4(0.f, 0.f, 0.f, 0.f);
    __syncthreads();

    const int lane = tid & 31, wid = tid >> 5;
    const int grp = lane >> 2, tg = lane & 3;

    const uint32_t* Ua0 = reinterpret_cast<const uint32_t*>(&Usm[grp * KS + 2 * tg]);
    const uint32_t* Ua1 = Ua0 + 8 * KS;
    const uint32_t* Wb  = reinterpret_cast<const uint32_t*>(&Wsm[(wid * 8 + grp) * KS + 2 * tg]);

    uint2 wreg[32];
#pragma unroll
    for (int ib = 0; ib < 32; ++ib)
        wreg[ib] = *reinterpret_cast<const uint2*>(Wb + ib * 8);

    const int bA   = rb0 + grp;
    const int colP = nc * NR + wid * 8 + 2 * tg;
    const float* xgA = xgscan + (size_t)bA * TT * G4H + colP;
    const float* xgB = xgA + (size_t)8 * TT * G4H;

    const bool odd  = (tg & 1);
    const int bl    = grp + (odd ? 8 : 0);
    const int jl    = 2 * wid + (tg >> 1);
    const int jslot = (jl & ~7) + (((jl & 3) << 1) | ((jl >> 2) & 1));

    const int sb = tid >> 4, sj = tid & 15;
    float* hout0 = &g_h[0][(rb0 + sb) * HH + nc * HC + sj];
    float* hout1 = &g_h[1][(rb0 + sb) * HH + nc * HC + sj];
    float* yown  = &Ydst[(size_t)(rb0 + bl) * TT * HH + nc * HC + jl];

    // front-of-step staging: warp wid stages producer slices 2*wid, 2*wid+1
    const int psl  = 2 * wid + (lane >> 4);
    const int prow = lane & 15;
    unsigned* pflag = &g_flags[bg][psl * 8];
    const float* hsrc0 = g_h[0] + (size_t)(rb0 + prow) * HH + psl * 16;
    const float* hsrc1 = g_h[1] + (size_t)(rb0 + prow) * HH + psl * 16;
    float* udst = &Usm[prow * KS + psl * 16];

    float c_state = 0.f;

    float2 x01 = *reinterpret_cast<const float2*>(xgA);
    float2 x23 = *reinterpret_cast<const float2*>(xgB);

    for (int t = 0; t < TT; ++t) {
        // ---- FRONT: per-warp poll of this warp's 2 producers, then stage
        if (t > 0) {
            const unsigned tgt = base + (unsigned)t;
            if ((lane & 15) == 0) {
                while (ld_acquire(pflag) < tgt) { }
            }
            __syncwarp();
            const float* hrow = (t & 1) ? hsrc1 : hsrc0;
#pragma unroll
            for (int q = 0; q < 4; ++q) {
                float4 v = __ldcg(reinterpret_cast<const float4*>(hrow + q * 4));
                *reinterpret_cast<float4*>(udst + q * 4) = v;
            }
        }
        __syncthreads();

        // ---- Whh * h_{t-1}: m16 x n8, K=256 as 4 chains, W in regs
        float a0c[4], a1c[4], a2c[4], a3c[4];
        a0c[0] = x01.x; a1c[0] = x01.y; a2c[0] = x23.x; a3c[0] = x23.y;
#pragma unroll
        for (int c = 1; c < 4; ++c) { a0c[c] = 0.f; a1c[c] = 0.f; a2c[c] = 0.f; a3c[c] = 0.f; }

#pragma unroll
        for (int kk = 0; kk < 8; ++kk) {
#pragma unroll
            for (int c = 0; c < 4; ++c) {
                int ib = c * 8 + kk;
                uint2 u0 = *reinterpret_cast<const uint2*>(Ua0 + ib * 8);
                uint2 u1 = *reinterpret_cast<const uint2*>(Ua1 + ib * 8);
                mma_tf32(a0c[c], a1c[c], a2c[c], a3c[c],
                         u0.x, u1.x, u0.y, u1.y, wreg[ib].x, wreg[ib].y);
            }
        }
        float c0 = (a0c[0] + a0c[1]) + (a0c[2] + a0c[3]);
        float c1 = (a1c[0] + a1c[1]) + (a1c[2] + a1c[3]);
        float c2 = (a2c[0] + a2c[1]) + (a2c[2] + a2c[3]);
        float c3 = (a3c[0] + a3c[1]) + (a3c[2] + a3c[3]);

        // ---- Gate exchange within lane pair (tg, tg^1)
        float s0 = odd ? c0 : c2;
        float s1 = odd ? c1 : c3;
        float r0 = __shfl_xor_sync(0xffffffffu, s0, 1);
        float r1 = __shfl_xor_sync(0xffffffffu, s1, 1);
        float iv = odd ? r0 : c0;
        float fv = odd ? r1 : c1;
        float gv = odd ? c2 : r0;
        float ov = odd ? c3 : r1;

        float is = sigf(iv);
        float fs = sigf(fv);
        float gt = tanh_fast(gv);
        float os = sigf(ov);
        c_state = fs * c_state + is * gt;
        float hn = os * tanh_fast(c_state);

        Hs[bl * HC + jslot] = to_tf32(hn);
        __syncthreads();

        // ---- Coalesced h store ONLY (Y deferred past the release)
        float hv = Hs[sb * HC + sj];
        if (t & 1) hout0[0] = hv; else hout1[0] = hv;   // write g_h[(t+1)&1]
        __syncthreads();   // h stores happen-before release

        if (tid == 0) st_release(myflag, base + (unsigned)(t + 1));

        // ---- Off the release path: Y store + xg prefetch
        yown[(size_t)t * HH] = hn;   // ordered by the NEXT release (gate is +1)
        if (t + 1 < TT) {
            xgA += G4H; xgB += G4H;
            x01 = *reinterpret_cast<const float2*>(xgA);
            x23 = *reinterpret_cast<const float2*>(xgB);
        }
    }

    // Final extra release: orders the last step's Y stores for the +1 gate.
    __syncthreads();
    if (tid == 0) st_release(myflag, base + (unsigned)(TT + 1));
}

// Final FC: out[b*T + t] = dot(Y0[b,t,:], fc_W) + fc_b. One warp per row.
__global__ void __launch_bounds__(256)
fc_kernel(const float* __restrict__ w, const float* __restrict__ bptr,
          float* __restrict__ out)
{
    int row  = blockIdx.x * 8 + (threadIdx.x >> 5);
    int lane = threadIdx.x & 31;
    const float* yr = g_Y0 + (size_t)row * HH;
    float4 a0 = *reinterpret_cast<const float4*>(yr + lane * 4);
    float4 a1 = *reinterpret_cast<const float4*>(yr + 128 + lane * 4);
    float4 w0 = *reinterpret_cast<const float4*>(w + lane * 4);
    float4 w1 = *reinterpret_cast<const float4*>(w + 128 + lane * 4);
    float s = a0.x * w0.x + a0.y * w0.y + a0.z * w0.z + a0.w * w0.w
            + a1.x * w1.x + a1.y * w1.y + a1.z * w1.z + a1.w * w1.w;
#pragma unroll
    for (int off = 16; off > 0; off >>= 1)
        s += __shfl_xor_sync(0xffffffffu, s, off);
    if (lane == 0) out[row] = s + bptr[0];
}

extern "C" void kernel_launch(void* const* d_in, const int* in_sizes, int n_in,
                              void* d_out, int out_size)
{
    const float* x        = (const float*)d_in[0];
    const float* Wih0     = (const float*)d_in[1];
    const float* Whh0     = (const float*)d_in[2];
    const float* Wih_rest = (const float*)d_in[3];
    const float* Whh_rest = (const float*)d_in[4];
    const float* bih      = (const float*)d_in[5];
    const float* bhh      = (const float*)d_in[6];
    const float* fcW      = (const float*)d_in[7];
    const float* fcb      = (const float*)d_in[8];
    float* out = (float*)d_out;

    size_t gsmem = (size_t)(2 * 128 * 72 + 2 * 256 * 72 + 256) * sizeof(float); // ~217 KB

    cudaFuncSetAttribute(xg0_kernel,
                         cudaFuncAttributeMaxDynamicSharedMemorySize, (int)gsmem);
    cudaFuncSetAttribute(mega_kernel,
                         cudaFuncAttributeMaxDynamicSharedMemorySize, (int)gsmem);

    // Single flag reset (flags are monotonic across layers)
    reset_kernel<<<1, NBG * NNC * 8>>>();

    // Layer 0 xg: x (K=128) -> g_XGa
    dim3 ggrid(G4H / 256, (BB * TT) / 128);   // 4 x 1024
    xg0_kernel<<<ggrid, 256, gsmem>>>(x, Wih0, bih, bhh);

    for (int l = 0; l < 5; ++l) {
        const float* Whh  = (l == 0) ? Whh0 : (Whh_rest + (size_t)(l - 1) * G4H * HH);
        const float* WihN = (l < 4) ? (Wih_rest + (size_t)l * G4H * HH) : Wih_rest;
        const float* biN  = bih + (size_t)((l < 4) ? (l + 1) : l) * G4H;
        const float* bhN  = bhh + (size_t)((l < 4) ? (l + 1) : l) * G4H;

        int nblocks = (l < 4) ? (128 + NGEMM) : 128;
        mega_kernel<<<nblocks, NTHREADS, gsmem>>>(
            /*ysel=*/l & 1, /*base=*/(unsigned)(l * LSTRIDE), Whh, WihN, biN, bhN);
    }

    // Layer 4 wrote Y0. FC head.
    fc_kernel<<<(BB * TT) / 8, 256>>>(fcW, fcb, out);
}

// round 16
// speedup vs baseline: 1.2803x; 1.0854x over previous
#include <cuda_runtime.h>
#include <stdint.h>
#include <math.h>

#define BB   128
#define TT   1024
#define DD   128
#define HH   256
#define G4H  1024

// Scan: 8 batch-groups x 16 N-slice CTAs = 128 CTAs, 256 threads each
#define NBG  8
#define NNC  16
#define BSUB 16
#define HC   16
#define NR   64
#define NTHREADS 256
#define KS   264
#define NGEMM 4096
#define LSTRIDE (TT + 16)   // per-layer flag base stride (room for the +1 release)

__device__ float    g_XGa[(size_t)BB * TT * G4H];
__device__ float    g_XGb[(size_t)BB * TT * G4H];
__device__ float    g_Y0[(size_t)BB * TT * HH];
__device__ float    g_Y1[(size_t)BB * TT * HH];
__device__ float    g_h[2][BB * HH];
__device__ unsigned g_flags[NBG][NNC * 8];

__global__ void reset_kernel() {
    if (threadIdx.x < NBG * NNC * 8)
        reinterpret_cast<unsigned*>(g_flags)[threadIdx.x] = 0u;
}

__device__ __forceinline__ float to_tf32(float x) {
    float r;
    asm("cvt.rna.tf32.f32 %0, %1;" : "=f"(r) : "f"(x));
    return r;
}

// HW tanh (sm_75+): single MUFU op
__device__ __forceinline__ float tanha(float x) {
    float r;
    asm("tanh.approx.f32 %0, %1;" : "=f"(r) : "f"(x));
    return r;
}
// sigmoid via HW tanh: 1 MUFU + 2 FMA
__device__ __forceinline__ float sigf(float x) {
    return fmaf(0.5f, tanha(0.5f * x), 0.5f);
}

__device__ __forceinline__ void mma_tf32(float& c0, float& c1, float& c2, float& c3,
                                         uint32_t a0, uint32_t a1, uint32_t a2, uint32_t a3,
                                         uint32_t b0, uint32_t b1) {
    asm volatile(
        "mma.sync.aligned.m16n8k8.row.col.f32.tf32.tf32.f32 "
        "{%0,%1,%2,%3}, {%4,%5,%6,%7}, {%8,%9}, {%0,%1,%2,%3};\n"
        : "+f"(c0), "+f"(c1), "+f"(c2), "+f"(c3)
        : "r"(a0), "r"(a1), "r"(a2), "r"(a3), "r"(b0), "r"(b1));
}

__device__ __forceinline__ void st_release(unsigned* p, unsigned v) {
    asm volatile("st.release.gpu.global.u32 [%0], %1;" :: "l"(p), "r"(v) : "memory");
}
__device__ __forceinline__ unsigned ld_acquire(unsigned* p) {
    unsigned v;
    asm volatile("ld.acquire.gpu.global.u32 %0, [%1];" : "=r"(v) : "l"(p) : "memory");
    return v;
}
__device__ __forceinline__ void cp_async16(uint32_t smem_addr, const void* gptr) {
    asm volatile("cp.async.cg.shared.global [%0], [%1], 16;" :: "r"(smem_addr), "l"(gptr));
}
__device__ __forceinline__ void cp_commit() { asm volatile("cp.async.commit_group;" ::: "memory"); }
template <int N>
__device__ __forceinline__ void cp_wait() { asm volatile("cp.async.wait_group %0;" :: "n"(N) : "memory"); }

__device__ __forceinline__ int kslot(int k) {
    return (k & ~7) + (((k & 3) << 1) | ((k >> 2) & 1));
}

// ============================================================================
// GEMM core (256 threads): 128m x 256n over K, cp.async dbl-buffered KC=64.
// ============================================================================
template <int K>
__device__ __forceinline__ void gemm_tile(
    float* smbase, const float* __restrict__ In, float* __restrict__ Out,
    const float* __restrict__ Wih,
    const float* __restrict__ bih, const float* __restrict__ bhh,
    int m0, int n0, int tid)
{
    constexpr int KC  = 64;
    constexpr int KSg = 72;
    constexpr int NC  = K / KC;
    float* As   = smbase;
    float* Bs   = As + 2 * 128 * KSg;
    float* bias = Bs + 2 * 256 * KSg;

    if (tid < 256) {
        int P  = n0 + tid;
        int bx = (P & 3) * HH + (P >> 2);
        bias[tid] = bih[bx] + bhh[bx];
    }

    const uint32_t sA = (uint32_t)__cvta_generic_to_shared(As);
    const uint32_t sB = (uint32_t)__cvta_generic_to_shared(Bs);

    auto stage = [&](int c) {
        int buf = c & 1;
        uint32_t dA = sA + (uint32_t)(buf * 128 * KSg) * 4;
        uint32_t dB = sB + (uint32_t)(buf * 256 * KSg) * 4;
        for (int idx = tid; idx < 128 * (KC / 4); idx += 256) {
            int r = idx >> 4, k4 = idx & 15;
            cp_async16(dA + (uint32_t)(r * KSg + k4 * 4) * 4,
                       In + (size_t)(m0 + r) * K + c * KC + k4 * 4);
        }
        for (int idx = tid; idx < 256 * (KC / 4); idx += 256) {
            int n = idx >> 4, k4 = idx & 15;
            int P  = n0 + n;
            int rw = (P & 3) * HH + (P >> 2);
            cp_async16(dB + (uint32_t)(n * KSg + k4 * 4) * 4,
                       Wih + (size_t)rw * K + c * KC + k4 * 4);
        }
        cp_commit();
    };

    const int lane = tid & 31, wid = tid >> 5;
    const int wm = wid >> 2, wn = wid & 3;
    const int grp = lane >> 2, tg = lane & 3;

    float acc[4][8][4];
#pragma unroll
    for (int mi = 0; mi < 4; ++mi)
#pragma unroll
        for (int ni = 0; ni < 8; ++ni)
#pragma unroll
            for (int q = 0; q < 4; ++q) acc[mi][ni][q] = 0.f;

    stage(0);

    for (int c = 0; c < NC; ++c) {
        if (c + 1 < NC) { stage(c + 1); cp_wait<1>(); }
        else           { cp_wait<0>(); }
        __syncthreads();

        const int buf = c & 1;
        const uint32_t* Ap = reinterpret_cast<const uint32_t*>(
            &As[buf * 128 * KSg + (wm * 64 + grp) * KSg + tg]);
        const uint32_t* Bp = reinterpret_cast<const uint32_t*>(
            &Bs[buf * 256 * KSg + (wn * 64 + grp) * KSg + tg]);

#pragma unroll
        for (int kt = 0; kt < KC / 8; ++kt) {
            uint32_t a[4][4];
#pragma unroll
            for (int mi = 0; mi < 4; ++mi) {
                const uint32_t* p = Ap + mi * 16 * KSg + kt * 8;
                a[mi][0] = p[0]; a[mi][1] = p[8 * KSg];
                a[mi][2] = p[4]; a[mi][3] = p[8 * KSg + 4];
            }
#pragma unroll
            for (int ni = 0; ni < 8; ++ni) {
                const uint32_t* q = Bp + ni * 8 * KSg + kt * 8;
                uint32_t b0 = q[0], b1 = q[4];
#pragma unroll
                for (int mi = 0; mi < 4; ++mi)
                    mma_tf32(acc[mi][ni][0], acc[mi][ni][1], acc[mi][ni][2], acc[mi][ni][3],
                             a[mi][0], a[mi][1], a[mi][2], a[mi][3], b0, b1);
            }
        }
        __syncthreads();
    }

#pragma unroll
    for (int mi = 0; mi < 4; ++mi)
#pragma unroll
        for (int ni = 0; ni < 8; ++ni) {
            int rl = wm * 64 + mi * 16 + grp;
            int cl = wn * 64 + ni * 8 + 2 * tg;
            float b0 = bias[cl], b1 = bias[cl + 1];
            size_t o = (size_t)(m0 + rl) * G4H + (n0 + cl);
            *reinterpret_cast<float2*>(&Out[o]) =
                make_float2(acc[mi][ni][0] + b0, acc[mi][ni][1] + b1);
            *reinterpret_cast<float2*>(&Out[o + (size_t)8 * G4H]) =
                make_float2(acc[mi][ni][2] + b0, acc[mi][ni][3] + b1);
        }
}

// Standalone xg GEMM for layer 0 (K = DD, reads x, writes g_XGa)
__global__ void __launch_bounds__(256, 1)
xg0_kernel(const float* __restrict__ x, const float* __restrict__ Wih,
           const float* __restrict__ bih, const float* __restrict__ bhh)
{
    extern __shared__ float sm[];
    gemm_tile<DD>(sm, x, g_XGa, Wih, bih, bhh,
                  blockIdx.y * 128, blockIdx.x * 256, threadIdx.x);
}

// ============================================================================
// Mega kernel: blockIdx < 128 -> LSTM scan (layer l). blockIdx >= 128 ->
// gated xg GEMM for layer l+1 (gate = +1 step: Y published lazily).
// Flags MONOTONIC across layers (base = l*LSTRIDE).
// ============================================================================
__global__ void __launch_bounds__(NTHREADS, 1)
mega_kernel(int ysel, unsigned base,
            const float* __restrict__ Whh,
            const float* __restrict__ WihN,
            const float* __restrict__ bihN, const float* __restrict__ bhhN)
{
    extern __shared__ float sm[];
    float* Ydst = (ysel == 0) ? g_Y0 : g_Y1;
    const float* xgscan = (ysel == 0) ? g_XGa : g_XGb;
    float*       xgnext = (ysel == 0) ? g_XGb : g_XGa;
    const int tid = threadIdx.x;

    if (blockIdx.x >= 128) {
        // ============ gated xg GEMM for layer l+1 (lazy-Y gate: +1) ============
        const int g   = blockIdx.x - 128;
        const int tc  = g >> 9;
        const int rem = g & 511;
        const int b   = rem >> 2;
        const int nb  = rem & 3;
        const int m0  = b * TT + tc * 128;
        const int n0  = nb * 256;

        if (tid < 32) {
            const unsigned need = base + (unsigned)((tc + 1) * 128 + 1);
            const int bgg = b >> 4;
            bool done;
            do {
                unsigned v = 0xffffffffu;
                if (tid < NNC) v = ld_acquire(&g_flags[bgg][tid * 8]);
                done = __all_sync(0xffffffffu, v >= need);
                if (!done) __nanosleep(256);
            } while (!done);
        }
        __syncthreads();

        gemm_tile<HH>(sm, Ydst, xgnext, WihN, bihN, bhhN, m0, n0, tid);
        return;
    }

    // ======================= LSTM scan (layer l) =======================
    float* Wsm = sm;              // [NR][KS]
    float* Usm = Wsm + NR * KS;   // [BSUB][KS]
    float* Hs  = Usm + BSUB * KS; // [BSUB*HC]

    const int cta = blockIdx.x;
    const int bg  = cta / NNC;
    const int nc  = cta % NNC;
    const int rb0 = bg * BSUB;
    unsigned* myflag = &g_flags[bg][nc * 8];

    for (int idx = tid; idx < NR * HH; idx += NTHREADS) {
        int rl = idx >> 8, k = idx & 255;
        int rw = (rl & 3) * HH + (nc * HC + (rl >> 2));
        Wsm[rl * KS + kslot(k)] = to_tf32(Whh[(size_t)rw * HH + k]);
    }
    for (int idx = tid * 4; idx < BSUB * KS; idx += NTHREADS * 4)
        *reinterpret_cast<float4*>(&Usm[idx]) = make_float4(0.f, 0.f, 0.f, 0.f);
    __syncthreads();

    const int lane = tid & 31, wid = tid >> 5;
    const int grp = lane >> 2, tg = lane & 3;

    const uint32_t* Ua0 = reinterpret_cast<const uint32_t*>(&Usm[grp * KS + 2 * tg]);
    const uint32_t* Ua1 = Ua0 + 8 * KS;
    const uint32_t* Wb  = reinterpret_cast<const uint32_t*>(&Wsm[(wid * 8 + grp) * KS + 2 * tg]);

    uint2 wreg[32];
#pragma unroll
    for (int ib = 0; ib < 32; ++ib)
        wreg[ib] = *reinterpret_cast<const uint2*>(Wb + ib * 8);

    const int bA   = rb0 + grp;
    const int colP = nc * NR + wid * 8 + 2 * tg;
    const float* xgA = xgscan + (size_t)bA * TT * G4H + colP;
    const float* xgB = xgA + (size_t)8 * TT * G4H;

    const bool odd  = (tg & 1);
    const int bl    = grp + (odd ? 8 : 0);
    const int jl    = 2 * wid + (tg >> 1);
    const int jslot = (jl & ~7) + (((jl & 3) << 1) | ((jl >> 2) & 1));

    const int sb = tid >> 4, sj = tid & 15;
    float* hout0 = &g_h[0][(rb0 + sb) * HH + nc * HC + sj];
    float* hout1 = &g_h[1][(rb0 + sb) * HH + nc * HC + sj];
    float* yown  = &Ydst[(size_t)(rb0 + bl) * TT * HH + nc * HC + jl];

    // front-of-step staging: warp wid stages producer slices 2*wid, 2*wid+1
    const int psl  = 2 * wid + (lane >> 4);
    const int prow = lane & 15;
    unsigned* pflag = &g_flags[bg][psl * 8];
    const float* hsrc0 = g_h[0] + (size_t)(rb0 + prow) * HH + psl * 16;
    const float* hsrc1 = g_h[1] + (size_t)(rb0 + prow) * HH + psl * 16;
    float* udst = &Usm[prow * KS + psl * 16];

    float c_state = 0.f;

    float2 x01 = *reinterpret_cast<const float2*>(xgA);
    float2 x23 = *reinterpret_cast<const float2*>(xgB);

    for (int t = 0; t < TT; ++t) {
        // ---- FRONT: per-warp poll of this warp's 2 producers, then stage
        if (t > 0) {
            const unsigned tgt = base + (unsigned)t;
            if ((lane & 15) == 0) {
                while (ld_acquire(pflag) < tgt) { }
            }
            __syncwarp();
            const float* hrow = (t & 1) ? hsrc1 : hsrc0;
#pragma unroll
            for (int q = 0; q < 4; ++q) {
                float4 v = __ldcg(reinterpret_cast<const float4*>(hrow + q * 4));
                *reinterpret_cast<float4*>(udst + q * 4) = v;
            }
        }
        __syncthreads();

        // ---- Whh * h_{t-1}: m16 x n8, K=256 as 4 chains, W in regs
        float a0c[4], a1c[4], a2c[4], a3c[4];
        a0c[0] = x01.x; a1c[0] = x01.y; a2c[0] = x23.x; a3c[0] = x23.y;
#pragma unroll
        for (int c = 1; c < 4; ++c) { a0c[c] = 0.f; a1c[c] = 0.f; a2c[c] = 0.f; a3c[c] = 0.f; }

#pragma unroll
        for (int kk = 0; kk < 8; ++kk) {
#pragma unroll
            for (int c = 0; c < 4; ++c) {
                int ib = c * 8 + kk;
                uint2 u0 = *reinterpret_cast<const uint2*>(Ua0 + ib * 8);
                uint2 u1 = *reinterpret_cast<const uint2*>(Ua1 + ib * 8);
                mma_tf32(a0c[c], a1c[c], a2c[c], a3c[c],
                         u0.x, u1.x, u0.y, u1.y, wreg[ib].x, wreg[ib].y);
            }
        }
        float c0 = (a0c[0] + a0c[1]) + (a0c[2] + a0c[3]);
        float c1 = (a1c[0] + a1c[1]) + (a1c[2] + a1c[3]);
        float c2 = (a2c[0] + a2c[1]) + (a2c[2] + a2c[3]);
        float c3 = (a3c[0] + a3c[1]) + (a3c[2] + a3c[3]);

        // ---- Gate exchange within lane pair (tg, tg^1)
        float s0 = odd ? c0 : c2;
        float s1 = odd ? c1 : c3;
        float r0 = __shfl_xor_sync(0xffffffffu, s0, 1);
        float r1 = __shfl_xor_sync(0xffffffffu, s1, 1);
        float iv = odd ? r0 : c0;
        float fv = odd ? r1 : c1;
        float gv = odd ? c2 : r0;
        float ov = odd ? c3 : r1;

        // ---- Activations: all through HW tanh (5 MUFU/thread total)
        float is = sigf(iv);
        float fs = sigf(fv);
        float gt = tanha(gv);
        float os = sigf(ov);
        c_state = fs * c_state + is * gt;
        float hn = os * tanha(c_state);

        Hs[bl * HC + jslot] = to_tf32(hn);
        __syncthreads();

        // ---- Coalesced h store ONLY (Y deferred past the release)
        float hv = Hs[sb * HC + sj];
        if (t & 1) hout0[0] = hv; else hout1[0] = hv;   // write g_h[(t+1)&1]
        __syncthreads();   // h stores happen-before release

        if (tid == 0) st_release(myflag, base + (unsigned)(t + 1));

        // ---- Off the release path: Y store + xg prefetch
        yown[(size_t)t * HH] = hn;   // ordered by the NEXT release (gate is +1)
        if (t + 1 < TT) {
            xgA += G4H; xgB += G4H;
            x01 = *reinterpret_cast<const float2*>(xgA);
            x23 = *reinterpret_cast<const float2*>(xgB);
        }
    }

    // Final extra release: orders the last step's Y stores for the +1 gate.
    __syncthreads();
    if (tid == 0) st_release(myflag, base + (unsigned)(TT + 1));
}

// Final FC: out[b*T + t] = dot(Y0[b,t,:], fc_W) + fc_b. One warp per row.
__global__ void __launch_bounds__(256)
fc_kernel(const float* __restrict__ w, const float* __restrict__ bptr,
          float* __restrict__ out)
{
    int row  = blockIdx.x * 8 + (threadIdx.x >> 5);
    int lane = threadIdx.x & 31;
    const float* yr = g_Y0 + (size_t)row * HH;
    float4 a0 = *reinterpret_cast<const float4*>(yr + lane * 4);
    float4 a1 = *reinterpret_cast<const float4*>(yr + 128 + lane * 4);
    float4 w0 = *reinterpret_cast<const float4*>(w + lane * 4);
    float4 w1 = *reinterpret_cast<const float4*>(w + 128 + lane * 4);
    float s = a0.x * w0.x + a0.y * w0.y + a0.z * w0.z + a0.w * w0.w
            + a1.x * w1.x + a1.y * w1.y + a1.z * w1.z + a1.w * w1.w;
#pragma unroll
    for (int off = 16; off > 0; off >>= 1)
        s += __shfl_xor_sync(0xffffffffu, s, off);
    if (lane == 0) out[row] = s + bptr[0];
}

extern "C" void kernel_launch(void* const* d_in, const int* in_sizes, int n_in,
                              void* d_out, int out_size)
{
    const float* x        = (const float*)d_in[0];
    const float* Wih0     = (const float*)d_in[1];
    const float* Whh0     = (const float*)d_in[2];
    const float* Wih_rest = (const float*)d_in[3];
    const float* Whh_rest = (const float*)d_in[4];
    const float* bih      = (const float*)d_in[5];
    const float* bhh      = (const float*)d_in[6];
    const float* fcW      = (const float*)d_in[7];
    const float* fcb      = (const float*)d_in[8];
    float* out = (float*)d_out;

    size_t gsmem = (size_t)(2 * 128 * 72 + 2 * 256 * 72 + 256) * sizeof(float); // ~217 KB

    cudaFuncSetAttribute(xg0_kernel,
                         cudaFuncAttributeMaxDynamicSharedMemorySize, (int)gsmem);
    cudaFuncSetAttribute(mega_kernel,
                         cudaFuncAttributeMaxDynamicSharedMemorySize, (int)gsmem);

    // Single flag reset (flags are monotonic across layers)
    reset_kernel<<<1, NBG * NNC * 8>>>();

    // Layer 0 xg: x (K=128) -> g_XGa
    dim3 ggrid(G4H / 256, (BB * TT) / 128);   // 4 x 1024
    xg0_kernel<<<ggrid, 256, gsmem>>>(x, Wih0, bih, bhh);

    for (int l = 0; l < 5; ++l) {
        const float* Whh  = (l == 0) ? Whh0 : (Whh_rest + (size_t)(l - 1) * G4H * HH);
        const float* WihN = (l < 4) ? (Wih_rest + (size_t)l * G4H * HH) : Wih_rest;
        const float* biN  = bih + (size_t)((l < 4) ? (l + 1) : l) * G4H;
        const float* bhN  = bhh + (size_t)((l < 4) ? (l + 1) : l) * G4H;

        int nblocks = (l < 4) ? (128 + NGEMM) : 128;
        mega_kernel<<<nblocks, NTHREADS, gsmem>>>(
            /*ysel=*/l & 1, /*base=*/(unsigned)(l * LSTRIDE), Whh, WihN, biN, bhN);
    }

    // Layer 4 wrote Y0. FC head.
    fc_kernel<<<(BB * TT) / 8, 256>>>(fcW, fcb, out);
}